// round 7
// baseline (speedup 1.0000x reference)
#include <cuda_runtime.h>
#include <cuda_bf16.h>
#include <cstdint>

#define N_MAX 50000
#define E_MAX 800000
#define D 128

// ---- scratch (__device__ globals; no cudaMalloc allowed) -------------------
__device__ float g_agg[N_MAX * D];     // pull-aggregated, nd-scaled [N,128]
__device__ float g_xs[N_MAX * D];      // X * ns prescaled [N,128]
__device__ int   g_deg_out[N_MAX];
__device__ int   g_deg_in[N_MAX];
__device__ int   g_off[N_MAX + 1];     // CSR offsets by dst
__device__ int   g_cursor[N_MAX];
__device__ int   g_esrc[E_MAX];        // src of each edge, bucketed by dst
__device__ float g_nd[N_MAX];          // rsqrt(max(deg_in,1))
__device__ float g_Wfused[D * D];      // W_conv @ W_aggr[0:128]
__device__ float g_bias[D];            // b_conv @ Wa1 + b_aggr

// ---------------------------------------------------------------------------
// K0: zero degree counters
__global__ void zero_kernel(int n) {
    int i = blockIdx.x * blockDim.x + threadIdx.x;
    if (i < n) { g_deg_out[i] = 0; g_deg_in[i] = 0; }
}

// K1: degree histograms
__global__ void deg_kernel(const int* __restrict__ src,
                           const int* __restrict__ dst, int E) {
    int i = blockIdx.x * blockDim.x + threadIdx.x;
    if (i < E) {
        atomicAdd(&g_deg_out[src[i]], 1);
        atomicAdd(&g_deg_in[dst[i]], 1);
    }
}

// K2: single-block exclusive scan of deg_in -> g_off / g_cursor
__global__ __launch_bounds__(1024) void scan_kernel(int n) {
    __shared__ int part[1024];
    int t = threadIdx.x;
    int chunk = (n + 1023) >> 10;
    int beg = t * chunk;
    int end = min(beg + chunk, n);
    int s = 0;
    for (int i = beg; i < end; i++) s += g_deg_in[i];
    part[t] = s;
    __syncthreads();
    for (int off = 1; off < 1024; off <<= 1) {
        int v = (t >= off) ? part[t - off] : 0;
        __syncthreads();
        part[t] += v;
        __syncthreads();
    }
    int run = (t == 0) ? 0 : part[t - 1];
    for (int i = beg; i < end; i++) {
        g_off[i] = run;
        g_cursor[i] = run;
        run += g_deg_in[i];
    }
    if (t == 1023) g_off[n] = part[1023];
}

// K3: bucket edges by dst
__global__ void bucket_kernel(const int* __restrict__ src,
                              const int* __restrict__ dst, int E) {
    int e = blockIdx.x * blockDim.x + threadIdx.x;
    if (e < E) {
        int d = __ldg(&dst[e]);
        int p = atomicAdd(&g_cursor[d], 1);
        g_esrc[p] = __ldg(&src[e]);
    }
}

// K4: prescale: g_xs[i] = X[i] * rsqrt(max(deg_out,1)); also g_nd.
__global__ __launch_bounds__(256) void prescale_kernel(
    const float4* __restrict__ X4, int n) {
    int t = blockIdx.x * 256 + threadIdx.x;
    int i = t >> 5, q = t & 31;
    if (i >= n) return;
    float ns = rsqrtf(fmaxf((float)__ldg(&g_deg_out[i]), 1.0f));
    if (q == 0)
        g_nd[i] = rsqrtf(fmaxf((float)__ldg(&g_deg_in[i]), 1.0f));
    float4 v = __ldg(&X4[t]);
    v.x *= ns; v.y *= ns; v.z *= ns; v.w *= ns;
    ((float4*)g_xs)[t] = v;
}

// K5: W_fused = Wc @ Wa1, bias = b_conv @ Wa1 + b_aggr. Split-K over 4 groups
// of 128 threads; 8 independent accumulators each; smem reduce.
__global__ __launch_bounds__(512) void fuse_kernel(
    const float* __restrict__ Wc,
    const float* __restrict__ Wa,
    const float* __restrict__ bc,
    const float* __restrict__ ba) {
    __shared__ float wc[D];
    __shared__ float part[4][D];
    int tid = threadIdx.x;
    int j = tid & 127;
    int g = tid >> 7;          // k-group 0..3
    int b = blockIdx.x;
    if (tid < D) wc[tid] = (b < D) ? __ldg(&Wc[b * D + tid]) : __ldg(&bc[tid]);
    __syncthreads();

    int k0 = g * 32;
    float a[8];
#pragma unroll
    for (int i = 0; i < 8; i++) a[i] = 0.f;
#pragma unroll
    for (int kk = 0; kk < 32; kk++)
        a[kk & 7] += wc[k0 + kk] * __ldg(&Wa[(k0 + kk) * D + j]);
    part[g][j] = ((a[0] + a[1]) + (a[2] + a[3])) + ((a[4] + a[5]) + (a[6] + a[7]));
    __syncthreads();
    if (g == 0) {
        float s = (part[0][j] + part[1][j]) + (part[2][j] + part[3][j]);
        if (b < D) g_Wfused[b * D + j] = s;
        else       g_bias[j] = s + __ldg(&ba[j]);
    }
}

// K6: pull aggregation — one warp per dst node, 4 independent gathers per
// iteration from prescaled g_xs; nd folded into the store. No atomics.
__global__ __launch_bounds__(256) void aggregate_kernel(int n) {
    int warp = (blockIdx.x * 256 + threadIdx.x) >> 5;
    int lane = threadIdx.x & 31;
    if (warp >= n) return;
    const float4* xs4 = (const float4*)g_xs;
    int beg = __ldg(&g_off[warp]);
    int end = __ldg(&g_off[warp + 1]);

    float4 acc = make_float4(0.f, 0.f, 0.f, 0.f);
    int j = beg;
    for (; j + 4 <= end; j += 4) {
        int s0 = __ldg(&g_esrc[j]);
        int s1 = __ldg(&g_esrc[j + 1]);
        int s2 = __ldg(&g_esrc[j + 2]);
        int s3 = __ldg(&g_esrc[j + 3]);
        float4 v0 = __ldg(&xs4[s0 * 32 + lane]);
        float4 v1 = __ldg(&xs4[s1 * 32 + lane]);
        float4 v2 = __ldg(&xs4[s2 * 32 + lane]);
        float4 v3 = __ldg(&xs4[s3 * 32 + lane]);
        acc.x += (v0.x + v1.x) + (v2.x + v3.x);
        acc.y += (v0.y + v1.y) + (v2.y + v3.y);
        acc.z += (v0.z + v1.z) + (v2.z + v3.z);
        acc.w += (v0.w + v1.w) + (v2.w + v3.w);
    }
    for (; j < end; j++) {
        int s0 = __ldg(&g_esrc[j]);
        float4 v0 = __ldg(&xs4[s0 * 32 + lane]);
        acc.x += v0.x; acc.y += v0.y; acc.z += v0.z; acc.w += v0.w;
    }
    float nd = __ldg(&g_nd[warp]);
    acc.x *= nd; acc.y *= nd; acc.z *= nd; acc.w *= nd;
    ((float4*)g_agg)[warp * 32 + lane] = acc;
}

// ---------------------------------------------------------------------------
// K7: tensor-core GEMM: out = g_agg @ W_fused + X @ Wa2 + bias
// (r6-proven version; nd already folded into g_agg)
#define KC 64
#define KPC (KC / 2)
#define A_STR 33
#define B_STR 136
#define SA_SZ (128 * A_STR)
#define SB_SZ (KPC * B_STR)
#define SM_U32 (2 * SA_SZ + 2 * SB_SZ)

#define MMA_BF16(c, a, b)                                                   \
    asm volatile(                                                           \
        "mma.sync.aligned.m16n8k16.row.col.f32.bf16.bf16.f32 "              \
        "{%0,%1,%2,%3}, {%4,%5,%6,%7}, {%8,%9}, {%0,%1,%2,%3};"             \
        : "+f"((c)[0]), "+f"((c)[1]), "+f"((c)[2]), "+f"((c)[3])            \
        : "r"((a)[0]), "r"((a)[1]), "r"((a)[2]), "r"((a)[3]),               \
          "r"((b)[0]), "r"((b)[1]))

__device__ __forceinline__ void split_pack(float v0, float v1,
                                           unsigned& hi, unsigned& lo) {
    __nv_bfloat162 h, l;
    h.x = __float2bfloat16(v0);
    h.y = __float2bfloat16(v1);
    l.x = __float2bfloat16(v0 - __bfloat162float(h.x));
    l.y = __float2bfloat16(v1 - __bfloat162float(h.y));
    hi = *(unsigned*)&h;
    lo = *(unsigned*)&l;
}

__global__ __launch_bounds__(256) void out_gemm_kernel(
    const float* __restrict__ X,
    const float* __restrict__ Wa2,
    float* __restrict__ out, int n) {
    extern __shared__ unsigned sm[];
    unsigned* sAh = sm;
    unsigned* sAl = sm + SA_SZ;
    unsigned* sBh = sm + 2 * SA_SZ;
    unsigned* sBl = sm + 2 * SA_SZ + SB_SZ;

    int tid = threadIdx.x;
    int wid = tid >> 5;
    int lane = tid & 31;
    int gid = lane >> 2;
    int tig = lane & 3;
    int wm = wid >> 2;
    int wn = wid & 3;
    int row0 = blockIdx.x * 128;

    float acc[4][4][4];
#pragma unroll
    for (int mt = 0; mt < 4; mt++)
#pragma unroll
        for (int nt = 0; nt < 4; nt++)
#pragma unroll
            for (int i = 0; i < 4; i++) acc[mt][nt][i] = 0.f;

#pragma unroll
    for (int phase = 0; phase < 2; phase++) {
        const float* Asrc = (phase == 0) ? g_agg : X;
        const float* Wsrc = (phase == 0) ? g_Wfused : Wa2;
#pragma unroll
        for (int ch = 0; ch < 2; ch++) {
            int k0 = ch * KC;
            // ---- stage A ---------------------------------------------------
#pragma unroll
            for (int it = 0; it < 8; it++) {
                int idx = tid + it * 256;
                int r = idx >> 4;
                int f4 = idx & 15;
                int grow = row0 + r;
                float4 v = make_float4(0.f, 0.f, 0.f, 0.f);
                if (grow < n)
                    v = ((const float4*)Asrc)[grow * 32 + (k0 >> 2) + f4];
                unsigned h0, l0, h1, l1;
                split_pack(v.x, v.y, h0, l0);
                split_pack(v.z, v.w, h1, l1);
                int o = r * A_STR + f4 * 2;
                sAh[o] = h0; sAh[o + 1] = h1;
                sAl[o] = l0; sAl[o + 1] = l1;
            }
            // ---- stage B ---------------------------------------------------
#pragma unroll
            for (int it = 0; it < 16; it++) {
                int idx = tid + it * 256;
                int kp = idx >> 7;
                int nn = idx & 127;
                float w0 = Wsrc[(k0 + 2 * kp) * D + nn];
                float w1 = Wsrc[(k0 + 2 * kp + 1) * D + nn];
                unsigned h, l;
                split_pack(w0, w1, h, l);
                sBh[kp * B_STR + nn] = h;
                sBl[kp * B_STR + nn] = l;
            }
            __syncthreads();

            // ---- mma over 4 k16 steps --------------------------------------
#pragma unroll
            for (int s = 0; s < 4; s++) {
                int kb = s * 8;
                unsigned bh[4][2], bl[4][2];
#pragma unroll
                for (int nt = 0; nt < 4; nt++) {
                    int col = wn * 32 + nt * 8 + gid;
                    bh[nt][0] = sBh[(kb + tig) * B_STR + col];
                    bh[nt][1] = sBh[(kb + tig + 4) * B_STR + col];
                    bl[nt][0] = sBl[(kb + tig) * B_STR + col];
                    bl[nt][1] = sBl[(kb + tig + 4) * B_STR + col];
                }
#pragma unroll
                for (int mt = 0; mt < 4; mt++) {
                    int rb = wm * 64 + mt * 16;
                    unsigned ah[4], al[4];
                    ah[0] = sAh[(rb + gid) * A_STR + kb + tig];
                    ah[1] = sAh[(rb + gid + 8) * A_STR + kb + tig];
                    ah[2] = sAh[(rb + gid) * A_STR + kb + tig + 4];
                    ah[3] = sAh[(rb + gid + 8) * A_STR + kb + tig + 4];
                    al[0] = sAl[(rb + gid) * A_STR + kb + tig];
                    al[1] = sAl[(rb + gid + 8) * A_STR + kb + tig];
                    al[2] = sAl[(rb + gid) * A_STR + kb + tig + 4];
                    al[3] = sAl[(rb + gid + 8) * A_STR + kb + tig + 4];
#pragma unroll
                    for (int nt = 0; nt < 4; nt++) {
                        MMA_BF16(acc[mt][nt], ah, bh[nt]);
                        MMA_BF16(acc[mt][nt], ah, bl[nt]);
                        MMA_BF16(acc[mt][nt], al, bh[nt]);
                    }
                }
            }
            __syncthreads();
        }
    }

    // ---- epilogue ----------------------------------------------------------
#pragma unroll
    for (int mt = 0; mt < 4; mt++) {
        int r = row0 + wm * 64 + mt * 16 + gid;
#pragma unroll
        for (int nt = 0; nt < 4; nt++) {
            int col = wn * 32 + nt * 8 + 2 * tig;
            float2 bv = *(const float2*)&g_bias[col];
            if (r < n) {
                float2 o0 = make_float2(acc[mt][nt][0] + bv.x,
                                        acc[mt][nt][1] + bv.y);
                *(float2*)&out[r * D + col] = o0;
            }
            if (r + 8 < n) {
                float2 o1 = make_float2(acc[mt][nt][2] + bv.x,
                                        acc[mt][nt][3] + bv.y);
                *(float2*)&out[(r + 8) * D + col] = o1;
            }
        }
    }
}

// ---------------------------------------------------------------------------
extern "C" void kernel_launch(void* const* d_in, const int* in_sizes, int n_in,
                              void* d_out, int out_size) {
    const float* features = (const float*)d_in[0];
    const int*   src      = (const int*)d_in[1];
    const int*   dst      = (const int*)d_in[2];
    const float* W_conv   = (const float*)d_in[3];
    const float* b_conv   = (const float*)d_in[4];
    const float* W_aggr   = (const float*)d_in[5];
    const float* b_aggr   = (const float*)d_in[6];
    float* out = (float*)d_out;

    int n = in_sizes[0] / D;
    int E = in_sizes[1];

    cudaFuncSetAttribute(out_gemm_kernel,
                         cudaFuncAttributeMaxDynamicSharedMemorySize,
                         SM_U32 * (int)sizeof(unsigned));

    zero_kernel<<<(n + 255) / 256, 256>>>(n);
    deg_kernel<<<(E + 255) / 256, 256>>>(src, dst, E);
    scan_kernel<<<1, 1024>>>(n);
    bucket_kernel<<<(E + 255) / 256, 256>>>(src, dst, E);
    prescale_kernel<<<(n * 32 + 255) / 256, 256>>>(
        (const float4*)features, n);
    fuse_kernel<<<D + 1, 512>>>(W_conv, W_aggr, b_conv, b_aggr);

    aggregate_kernel<<<(n * 32 + 255) / 256, 256>>>(n);

    out_gemm_kernel<<<(n + 127) / 128, 256, SM_U32 * (int)sizeof(unsigned)>>>(
        features, W_aggr + D * D, out, n);
}

// round 8
// speedup vs baseline: 1.2186x; 1.2186x over previous
#include <cuda_runtime.h>
#include <cuda_bf16.h>
#include <cstdint>

#define N_MAX 50000
#define D 128

// ---- scratch (__device__ globals; no cudaMalloc allowed) -------------------
__device__ float g_agg[N_MAX * D];     // scatter accumulator [N,128]
__device__ int   g_deg_out[N_MAX];
__device__ int   g_deg_in[N_MAX];
__device__ float g_ns[N_MAX];          // rsqrt(max(deg_out,1))
__device__ float g_nd[N_MAX];          // rsqrt(max(deg_in,1))
__device__ float g_Wfused[D * D];      // W_conv @ W_aggr[0:128]
__device__ float g_bias[D];            // b_conv @ Wa1 + b_aggr

// ---------------------------------------------------------------------------
// K0: zero agg + degree counters
__global__ void zero_kernel(int n) {
    int i = blockIdx.x * blockDim.x + threadIdx.x;
    int nf4 = n * (D / 4);
    if (i < nf4) ((float4*)g_agg)[i] = make_float4(0.f, 0.f, 0.f, 0.f);
    if (i < n) { g_deg_out[i] = 0; g_deg_in[i] = 0; }
}

// K1: degree histograms
__global__ void deg_kernel(const int* __restrict__ src,
                           const int* __restrict__ dst, int E) {
    int i = blockIdx.x * blockDim.x + threadIdx.x;
    if (i < E) {
        atomicAdd(&g_deg_out[src[i]], 1);
        atomicAdd(&g_deg_in[dst[i]], 1);
    }
}

// K2: normalization factors
__global__ void norm_kernel(int n) {
    int i = blockIdx.x * blockDim.x + threadIdx.x;
    if (i < n) {
        g_ns[i] = rsqrtf(fmaxf((float)g_deg_out[i], 1.0f));
        g_nd[i] = rsqrtf(fmaxf((float)g_deg_in[i], 1.0f));
    }
}

// K3: W_fused = Wc @ Wa1, bias = b_conv @ Wa1 + b_aggr.
// Split-K: 512 threads/row = 4 k-groups x 128 cols, 8 indep accumulators
// per group (MLP ~32), smem reduce.
__global__ __launch_bounds__(512) void fuse_kernel(
    const float* __restrict__ Wc,
    const float* __restrict__ Wa,
    const float* __restrict__ bc,
    const float* __restrict__ ba) {
    __shared__ float wc[D];
    __shared__ float part[4][D];
    int tid = threadIdx.x;
    int j = tid & 127;
    int g = tid >> 7;          // k-group 0..3
    int b = blockIdx.x;
    if (tid < D) wc[tid] = (b < D) ? __ldg(&Wc[b * D + tid]) : __ldg(&bc[tid]);
    __syncthreads();

    int k0 = g * 32;
    float a[8];
#pragma unroll
    for (int i = 0; i < 8; i++) a[i] = 0.f;
#pragma unroll
    for (int kk = 0; kk < 32; kk++)
        a[kk & 7] += wc[k0 + kk] * __ldg(&Wa[(k0 + kk) * D + j]);
    part[g][j] = ((a[0] + a[1]) + (a[2] + a[3])) + ((a[4] + a[5]) + (a[6] + a[7]));
    __syncthreads();
    if (g == 0) {
        float s = (part[0][j] + part[1][j]) + (part[2][j] + part[3][j]);
        if (b < D) g_Wfused[b * D + j] = s;
        else       g_bias[j] = s + __ldg(&ba[j]);
    }
}

// K4: scatter-add: agg[dst[e]] += X[src[e]] * ns[src[e]]  (one warp per edge)
__global__ __launch_bounds__(256) void scatter_kernel(
    const float4* __restrict__ X4,
    const int* __restrict__ src,
    const int* __restrict__ dst, int E) {
    int gt = blockIdx.x * 256 + threadIdx.x;
    int e = gt >> 5;
    int lane = gt & 31;
    if (e >= E) return;
    int s = __ldg(&src[e]);
    int d = __ldg(&dst[e]);
    float ns = g_ns[s];
    float4 v = X4[s * 32 + lane];
    v.x *= ns; v.y *= ns; v.z *= ns; v.w *= ns;
    float4* p = ((float4*)g_agg) + d * 32 + lane;
    asm volatile("red.global.add.v4.f32 [%0], {%1,%2,%3,%4};"
                 :: "l"(p), "f"(v.x), "f"(v.y), "f"(v.z), "f"(v.w)
                 : "memory");
}

// ---------------------------------------------------------------------------
// K5: tensor-core GEMM: out = (agg*nd) @ W_fused + X @ Wa2 + bias
// bf16 error-compensated split (hi*hi + hi*lo + lo*hi), fp32 accumulate.
#define KC 64
#define KPC (KC / 2)
#define A_STR 33
#define B_STR 136
#define SA_SZ (128 * A_STR)
#define SB_SZ (KPC * B_STR)
#define SM_U32 (2 * SA_SZ + 2 * SB_SZ)

#define MMA_BF16(c, a, b)                                                   \
    asm volatile(                                                           \
        "mma.sync.aligned.m16n8k16.row.col.f32.bf16.bf16.f32 "              \
        "{%0,%1,%2,%3}, {%4,%5,%6,%7}, {%8,%9}, {%0,%1,%2,%3};"             \
        : "+f"((c)[0]), "+f"((c)[1]), "+f"((c)[2]), "+f"((c)[3])            \
        : "r"((a)[0]), "r"((a)[1]), "r"((a)[2]), "r"((a)[3]),               \
          "r"((b)[0]), "r"((b)[1]))

// fast split: hi = rn-bf16x2(v0,v1); hi-as-f32 via bf16bits<<16; lo = rn-bf16x2
// of the residuals. ~6 instrs vs ~10 for the elementwise version.
__device__ __forceinline__ void split_pack(float v0, float v1,
                                           unsigned& hi, unsigned& lo) {
    unsigned h;
    asm("cvt.rn.bf16x2.f32 %0, %1, %2;" : "=r"(h) : "f"(v1), "f"(v0));
    float f0 = __uint_as_float(h << 16);
    float f1 = __uint_as_float(h & 0xffff0000u);
    float r0 = v0 - f0;
    float r1 = v1 - f1;
    unsigned l;
    asm("cvt.rn.bf16x2.f32 %0, %1, %2;" : "=r"(l) : "f"(r1), "f"(r0));
    hi = h;
    lo = l;
}

__global__ __launch_bounds__(256) void out_gemm_kernel(
    const float* __restrict__ X,
    const float* __restrict__ Wa2,
    float* __restrict__ out, int n) {
    extern __shared__ unsigned sm[];
    unsigned* sAh = sm;
    unsigned* sAl = sm + SA_SZ;
    unsigned* sBh = sm + 2 * SA_SZ;
    unsigned* sBl = sm + 2 * SA_SZ + SB_SZ;

    int tid = threadIdx.x;
    int wid = tid >> 5;
    int lane = tid & 31;
    int gid = lane >> 2;
    int tig = lane & 3;
    int wm = wid >> 2;
    int wn = wid & 3;
    int row0 = blockIdx.x * 128;

    float acc[4][4][4];
#pragma unroll
    for (int mt = 0; mt < 4; mt++)
#pragma unroll
        for (int nt = 0; nt < 4; nt++)
#pragma unroll
            for (int i = 0; i < 4; i++) acc[mt][nt][i] = 0.f;

#pragma unroll
    for (int phase = 0; phase < 2; phase++) {
        const float* Asrc = (phase == 0) ? g_agg : X;
        const float* Wsrc = (phase == 0) ? g_Wfused : Wa2;
#pragma unroll
        for (int ch = 0; ch < 2; ch++) {
            int k0 = ch * KC;
            // ---- stage A: 128 rows x 64 cols -> packed bf16 pairs --------
#pragma unroll
            for (int it = 0; it < 8; it++) {
                int idx = tid + it * 256;
                int r = idx >> 4;
                int f4 = idx & 15;
                int grow = row0 + r;
                float4 v = make_float4(0.f, 0.f, 0.f, 0.f);
                if (grow < n) {
                    v = ((const float4*)Asrc)[grow * 32 + (k0 >> 2) + f4];
                    if (phase == 0) {
                        float nd = g_nd[grow];
                        v.x *= nd; v.y *= nd; v.z *= nd; v.w *= nd;
                    }
                }
                unsigned h0, l0, h1, l1;
                split_pack(v.x, v.y, h0, l0);
                split_pack(v.z, v.w, h1, l1);
                int o = r * A_STR + f4 * 2;
                sAh[o] = h0; sAh[o + 1] = h1;
                sAl[o] = l0; sAl[o + 1] = l1;
            }
            // ---- stage B: 64 k x 128 n -> packed [kpair][n] ---------------
#pragma unroll
            for (int it = 0; it < 16; it++) {
                int idx = tid + it * 256;
                int kp = idx >> 7;
                int nn = idx & 127;
                float w0 = Wsrc[(k0 + 2 * kp) * D + nn];
                float w1 = Wsrc[(k0 + 2 * kp + 1) * D + nn];
                unsigned h, l;
                split_pack(w0, w1, h, l);
                sBh[kp * B_STR + nn] = h;
                sBl[kp * B_STR + nn] = l;
            }
            __syncthreads();

            // ---- mma over 4 k16 steps ------------------------------------
#pragma unroll
            for (int s = 0; s < 4; s++) {
                int kb = s * 8;
                unsigned bh[4][2], bl[4][2];
#pragma unroll
                for (int nt = 0; nt < 4; nt++) {
                    int col = wn * 32 + nt * 8 + gid;
                    bh[nt][0] = sBh[(kb + tig) * B_STR + col];
                    bh[nt][1] = sBh[(kb + tig + 4) * B_STR + col];
                    bl[nt][0] = sBl[(kb + tig) * B_STR + col];
                    bl[nt][1] = sBl[(kb + tig + 4) * B_STR + col];
                }
#pragma unroll
                for (int mt = 0; mt < 4; mt++) {
                    int rb = wm * 64 + mt * 16;
                    unsigned ah[4], al[4];
                    ah[0] = sAh[(rb + gid) * A_STR + kb + tig];
                    ah[1] = sAh[(rb + gid + 8) * A_STR + kb + tig];
                    ah[2] = sAh[(rb + gid) * A_STR + kb + tig + 4];
                    ah[3] = sAh[(rb + gid + 8) * A_STR + kb + tig + 4];
                    al[0] = sAl[(rb + gid) * A_STR + kb + tig];
                    al[1] = sAl[(rb + gid + 8) * A_STR + kb + tig];
                    al[2] = sAl[(rb + gid) * A_STR + kb + tig + 4];
                    al[3] = sAl[(rb + gid + 8) * A_STR + kb + tig + 4];
#pragma unroll
                    for (int nt = 0; nt < 4; nt++) {
                        MMA_BF16(acc[mt][nt], ah, bh[nt]);  // hi*hi
                        MMA_BF16(acc[mt][nt], ah, bl[nt]);  // hi*lo
                        MMA_BF16(acc[mt][nt], al, bh[nt]);  // lo*hi
                    }
                }
            }
            __syncthreads();
        }
    }

    // ---- epilogue: bias + store ------------------------------------------
#pragma unroll
    for (int mt = 0; mt < 4; mt++) {
        int r = row0 + wm * 64 + mt * 16 + gid;
#pragma unroll
        for (int nt = 0; nt < 4; nt++) {
            int col = wn * 32 + nt * 8 + 2 * tig;
            float2 bv = *(const float2*)&g_bias[col];
            if (r < n) {
                float2 o0 = make_float2(acc[mt][nt][0] + bv.x,
                                        acc[mt][nt][1] + bv.y);
                *(float2*)&out[r * D + col] = o0;
            }
            if (r + 8 < n) {
                float2 o1 = make_float2(acc[mt][nt][2] + bv.x,
                                        acc[mt][nt][3] + bv.y);
                *(float2*)&out[(r + 8) * D + col] = o1;
            }
        }
    }
}

// ---------------------------------------------------------------------------
extern "C" void kernel_launch(void* const* d_in, const int* in_sizes, int n_in,
                              void* d_out, int out_size) {
    const float* features = (const float*)d_in[0];
    const int*   src      = (const int*)d_in[1];
    const int*   dst      = (const int*)d_in[2];
    const float* W_conv   = (const float*)d_in[3];
    const float* b_conv   = (const float*)d_in[4];
    const float* W_aggr   = (const float*)d_in[5];
    const float* b_aggr   = (const float*)d_in[6];
    float* out = (float*)d_out;

    int n = in_sizes[0] / D;
    int E = in_sizes[1];

    cudaFuncSetAttribute(out_gemm_kernel,
                         cudaFuncAttributeMaxDynamicSharedMemorySize,
                         SM_U32 * (int)sizeof(unsigned));

    int nf4 = n * (D / 4);
    zero_kernel<<<(nf4 + 255) / 256, 256>>>(n);
    deg_kernel<<<(E + 255) / 256, 256>>>(src, dst, E);
    norm_kernel<<<(n + 255) / 256, 256>>>(n);
    fuse_kernel<<<D + 1, 512>>>(W_conv, W_aggr, b_conv, b_aggr);

    long long threads = (long long)E * 32;
    scatter_kernel<<<(int)((threads + 255) / 256), 256>>>(
        (const float4*)features, src, dst, E);

    out_gemm_kernel<<<(n + 127) / 128, 256, SM_U32 * (int)sizeof(unsigned)>>>(
        features, W_aggr + D * D, out, n);
}

// round 9
// speedup vs baseline: 1.2585x; 1.0328x over previous
#include <cuda_runtime.h>
#include <cuda_bf16.h>
#include <cstdint>

#define N_MAX 50000
#define D 128

// ---- scratch (__device__ globals; no cudaMalloc allowed) -------------------
__device__ float g_agg[N_MAX * D];     // scatter accumulator [N,128]
__device__ int   g_deg_out[N_MAX];
__device__ int   g_deg_in[N_MAX];
__device__ float g_ns[N_MAX];          // rsqrt(max(deg_out,1))
__device__ float g_nd[N_MAX];          // rsqrt(max(deg_in,1))
__device__ float g_Wfused[D * D];      // W_conv @ W_aggr[0:128]
__device__ float g_bias[D];            // b_conv @ Wa1 + b_aggr

// ---------------------------------------------------------------------------
// K0: zero agg + degree counters
__global__ void zero_kernel(int n) {
    int i = blockIdx.x * blockDim.x + threadIdx.x;
    int nf4 = n * (D / 4);
    if (i < nf4) ((float4*)g_agg)[i] = make_float4(0.f, 0.f, 0.f, 0.f);
    if (i < n) { g_deg_out[i] = 0; g_deg_in[i] = 0; }
}

// K1: degree histograms
__global__ void deg_kernel(const int* __restrict__ src,
                           const int* __restrict__ dst, int E) {
    int i = blockIdx.x * blockDim.x + threadIdx.x;
    if (i < E) {
        atomicAdd(&g_deg_out[src[i]], 1);
        atomicAdd(&g_deg_in[dst[i]], 1);
    }
}

// K2: normalization factors
__global__ void norm_kernel(int n) {
    int i = blockIdx.x * blockDim.x + threadIdx.x;
    if (i < n) {
        g_ns[i] = rsqrtf(fmaxf((float)g_deg_out[i], 1.0f));
        g_nd[i] = rsqrtf(fmaxf((float)g_deg_in[i], 1.0f));
    }
}

// K3: W_fused = Wc @ Wa1, bias = b_conv @ Wa1 + b_aggr (split-K, r8-proven)
__global__ __launch_bounds__(512) void fuse_kernel(
    const float* __restrict__ Wc,
    const float* __restrict__ Wa,
    const float* __restrict__ bc,
    const float* __restrict__ ba) {
    __shared__ float wc[D];
    __shared__ float part[4][D];
    int tid = threadIdx.x;
    int j = tid & 127;
    int g = tid >> 7;
    int b = blockIdx.x;
    if (tid < D) wc[tid] = (b < D) ? __ldg(&Wc[b * D + tid]) : __ldg(&bc[tid]);
    __syncthreads();

    int k0 = g * 32;
    float a[8];
#pragma unroll
    for (int i = 0; i < 8; i++) a[i] = 0.f;
#pragma unroll
    for (int kk = 0; kk < 32; kk++)
        a[kk & 7] += wc[k0 + kk] * __ldg(&Wa[(k0 + kk) * D + j]);
    part[g][j] = ((a[0] + a[1]) + (a[2] + a[3])) + ((a[4] + a[5]) + (a[6] + a[7]));
    __syncthreads();
    if (g == 0) {
        float s = (part[0][j] + part[1][j]) + (part[2][j] + part[3][j]);
        if (b < D) g_Wfused[b * D + j] = s;
        else       g_bias[j] = s + __ldg(&ba[j]);
    }
}

// K4: scatter-add — TWO edges per warp, independent chains for MLP=2/warp.
__global__ __launch_bounds__(256) void scatter_kernel(
    const float4* __restrict__ X4,
    const int* __restrict__ src,
    const int* __restrict__ dst, int E) {
    int gt = blockIdx.x * 256 + threadIdx.x;
    int w = gt >> 5;
    int lane = gt & 31;
    int e0 = 2 * w;
    int e1 = e0 + 1;
    if (e0 >= E) return;
    bool has1 = (e1 < E);

    int s0 = __ldg(&src[e0]);
    int d0 = __ldg(&dst[e0]);
    int s1 = has1 ? __ldg(&src[e1]) : s0;
    int d1 = has1 ? __ldg(&dst[e1]) : d0;
    float ns0 = __ldg(&g_ns[s0]);
    float ns1 = __ldg(&g_ns[s1]);
    float4 v0 = __ldg(&X4[s0 * 32 + lane]);
    float4 v1 = __ldg(&X4[s1 * 32 + lane]);
    v0.x *= ns0; v0.y *= ns0; v0.z *= ns0; v0.w *= ns0;
    v1.x *= ns1; v1.y *= ns1; v1.z *= ns1; v1.w *= ns1;

    float4* p0 = ((float4*)g_agg) + d0 * 32 + lane;
    asm volatile("red.global.add.v4.f32 [%0], {%1,%2,%3,%4};"
                 :: "l"(p0), "f"(v0.x), "f"(v0.y), "f"(v0.z), "f"(v0.w)
                 : "memory");
    if (has1) {
        float4* p1 = ((float4*)g_agg) + d1 * 32 + lane;
        asm volatile("red.global.add.v4.f32 [%0], {%1,%2,%3,%4};"
                     :: "l"(p1), "f"(v1.x), "f"(v1.y), "f"(v1.z), "f"(v1.w)
                     : "memory");
    }
}

// ---------------------------------------------------------------------------
// K5: tensor-core GEMM: out = (agg*nd) @ W_fused + X @ Wa2 + bias
#define KC 64
#define KPC (KC / 2)
#define A_STR 33
#define B_STR 136
#define SA_SZ (128 * A_STR)
#define SB_SZ (KPC * B_STR)
#define SM_U32 (2 * SA_SZ + 2 * SB_SZ)

#define MMA_BF16(c, a, b)                                                   \
    asm volatile(                                                           \
        "mma.sync.aligned.m16n8k16.row.col.f32.bf16.bf16.f32 "              \
        "{%0,%1,%2,%3}, {%4,%5,%6,%7}, {%8,%9}, {%0,%1,%2,%3};"             \
        : "+f"((c)[0]), "+f"((c)[1]), "+f"((c)[2]), "+f"((c)[3])            \
        : "r"((a)[0]), "r"((a)[1]), "r"((a)[2]), "r"((a)[3]),               \
          "r"((b)[0]), "r"((b)[1]))

// fast split: hi = rn-bf16x2(v0,v1); hi-as-f32 via bit tricks; lo likewise.
__device__ __forceinline__ void split_pack(float v0, float v1,
                                           unsigned& hi, unsigned& lo) {
    unsigned h;
    asm("cvt.rn.bf16x2.f32 %0, %1, %2;" : "=r"(h) : "f"(v1), "f"(v0));
    float f0 = __uint_as_float(h << 16);
    float f1 = __uint_as_float(h & 0xffff0000u);
    float r0 = v0 - f0;
    float r1 = v1 - f1;
    unsigned l;
    asm("cvt.rn.bf16x2.f32 %0, %1, %2;" : "=r"(l) : "f"(r1), "f"(r0));
    hi = h;
    lo = l;
}

__global__ __launch_bounds__(256) void out_gemm_kernel(
    const float* __restrict__ X,
    const float* __restrict__ Wa2,
    float* __restrict__ out, int n) {
    extern __shared__ unsigned sm[];
    unsigned* sAh = sm;
    unsigned* sAl = sm + SA_SZ;
    unsigned* sBh = sm + 2 * SA_SZ;
    unsigned* sBl = sm + 2 * SA_SZ + SB_SZ;

    int tid = threadIdx.x;
    int wid = tid >> 5;
    int lane = tid & 31;
    int gid = lane >> 2;
    int tig = lane & 3;
    int wm = wid >> 2;
    int wn = wid & 3;
    int row0 = blockIdx.x * 128;

    float acc[4][4][4];
#pragma unroll
    for (int mt = 0; mt < 4; mt++)
#pragma unroll
        for (int nt = 0; nt < 4; nt++)
#pragma unroll
            for (int i = 0; i < 4; i++) acc[mt][nt][i] = 0.f;

#pragma unroll
    for (int phase = 0; phase < 2; phase++) {
        const float* Asrc = (phase == 0) ? g_agg : X;
        const float* Wsrc = (phase == 0) ? g_Wfused : Wa2;
#pragma unroll
        for (int ch = 0; ch < 2; ch++) {
            int k0 = ch * KC;
            // ---- stage A: 128 rows x 64 cols -> packed bf16 pairs --------
#pragma unroll
            for (int it = 0; it < 8; it++) {
                int idx = tid + it * 256;
                int r = idx >> 4;
                int f4 = idx & 15;
                int grow = row0 + r;
                float4 v = make_float4(0.f, 0.f, 0.f, 0.f);
                if (grow < n) {
                    v = ((const float4*)Asrc)[grow * 32 + (k0 >> 2) + f4];
                    if (phase == 0) {
                        float nd = g_nd[grow];
                        v.x *= nd; v.y *= nd; v.z *= nd; v.w *= nd;
                    }
                }
                unsigned h0, l0, h1, l1;
                split_pack(v.x, v.y, h0, l0);
                split_pack(v.z, v.w, h1, l1);
                int o = r * A_STR + f4 * 2;
                sAh[o] = h0; sAh[o + 1] = h1;
                sAl[o] = l0; sAl[o + 1] = l1;
            }
            // ---- stage B: float4 loads, 4 columns x 2 k-rows per task ----
            // task idx: kp = idx>>5 (kpair 0..31), c = idx&31 (col group of 4)
#pragma unroll
            for (int it = 0; it < 4; it++) {
                int idx = tid + it * 256;
                int kp = idx >> 5;
                int c = idx & 31;
                float4 wa = *(const float4*)&Wsrc[(k0 + 2 * kp) * D + 4 * c];
                float4 wb = *(const float4*)&Wsrc[(k0 + 2 * kp + 1) * D + 4 * c];
                unsigned h0, l0, h1, l1, h2, l2, h3, l3;
                split_pack(wa.x, wb.x, h0, l0);
                split_pack(wa.y, wb.y, h1, l1);
                split_pack(wa.z, wb.z, h2, l2);
                split_pack(wa.w, wb.w, h3, l3);
                int o = kp * B_STR + 4 * c;
                *(uint4*)&sBh[o] = make_uint4(h0, h1, h2, h3);
                *(uint4*)&sBl[o] = make_uint4(l0, l1, l2, l3);
            }
            __syncthreads();

            // ---- mma over 4 k16 steps ------------------------------------
#pragma unroll
            for (int s = 0; s < 4; s++) {
                int kb = s * 8;
                unsigned bh[4][2], bl[4][2];
#pragma unroll
                for (int nt = 0; nt < 4; nt++) {
                    int col = wn * 32 + nt * 8 + gid;
                    bh[nt][0] = sBh[(kb + tig) * B_STR + col];
                    bh[nt][1] = sBh[(kb + tig + 4) * B_STR + col];
                    bl[nt][0] = sBl[(kb + tig) * B_STR + col];
                    bl[nt][1] = sBl[(kb + tig + 4) * B_STR + col];
                }
#pragma unroll
                for (int mt = 0; mt < 4; mt++) {
                    int rb = wm * 64 + mt * 16;
                    unsigned ah[4], al[4];
                    ah[0] = sAh[(rb + gid) * A_STR + kb + tig];
                    ah[1] = sAh[(rb + gid + 8) * A_STR + kb + tig];
                    ah[2] = sAh[(rb + gid) * A_STR + kb + tig + 4];
                    ah[3] = sAh[(rb + gid + 8) * A_STR + kb + tig + 4];
                    al[0] = sAl[(rb + gid) * A_STR + kb + tig];
                    al[1] = sAl[(rb + gid + 8) * A_STR + kb + tig];
                    al[2] = sAl[(rb + gid) * A_STR + kb + tig + 4];
                    al[3] = sAl[(rb + gid + 8) * A_STR + kb + tig + 4];
#pragma unroll
                    for (int nt = 0; nt < 4; nt++) {
                        MMA_BF16(acc[mt][nt], ah, bh[nt]);  // hi*hi
                        MMA_BF16(acc[mt][nt], ah, bl[nt]);  // hi*lo
                        MMA_BF16(acc[mt][nt], al, bh[nt]);  // lo*hi
                    }
                }
            }
            __syncthreads();
        }
    }

    // ---- epilogue: bias + store ------------------------------------------
#pragma unroll
    for (int mt = 0; mt < 4; mt++) {
        int r = row0 + wm * 64 + mt * 16 + gid;
#pragma unroll
        for (int nt = 0; nt < 4; nt++) {
            int col = wn * 32 + nt * 8 + 2 * tig;
            float2 bv = *(const float2*)&g_bias[col];
            if (r < n) {
                float2 o0 = make_float2(acc[mt][nt][0] + bv.x,
                                        acc[mt][nt][1] + bv.y);
                *(float2*)&out[r * D + col] = o0;
            }
            if (r + 8 < n) {
                float2 o1 = make_float2(acc[mt][nt][2] + bv.x,
                                        acc[mt][nt][3] + bv.y);
                *(float2*)&out[(r + 8) * D + col] = o1;
            }
        }
    }
}

// ---------------------------------------------------------------------------
extern "C" void kernel_launch(void* const* d_in, const int* in_sizes, int n_in,
                              void* d_out, int out_size) {
    const float* features = (const float*)d_in[0];
    const int*   src      = (const int*)d_in[1];
    const int*   dst      = (const int*)d_in[2];
    const float* W_conv   = (const float*)d_in[3];
    const float* b_conv   = (const float*)d_in[4];
    const float* W_aggr   = (const float*)d_in[5];
    const float* b_aggr   = (const float*)d_in[6];
    float* out = (float*)d_out;

    int n = in_sizes[0] / D;
    int E = in_sizes[1];

    cudaFuncSetAttribute(out_gemm_kernel,
                         cudaFuncAttributeMaxDynamicSharedMemorySize,
                         SM_U32 * (int)sizeof(unsigned));

    int nf4 = n * (D / 4);
    zero_kernel<<<(nf4 + 255) / 256, 256>>>(n);
    deg_kernel<<<(E + 255) / 256, 256>>>(src, dst, E);
    norm_kernel<<<(n + 255) / 256, 256>>>(n);
    fuse_kernel<<<D + 1, 512>>>(W_conv, W_aggr, b_conv, b_aggr);

    long long nwarps = ((long long)E + 1) / 2;
    long long threads = nwarps * 32;
    scatter_kernel<<<(int)((threads + 255) / 256), 256>>>(
        (const float4*)features, src, dst, E);

    out_gemm_kernel<<<(n + 127) / 128, 256, SM_U32 * (int)sizeof(unsigned)>>>(
        features, W_aggr + D * D, out, n);
}